// round 15
// baseline (speedup 1.0000x reference)
#include <cuda_runtime.h>
#include <cstdint>

// BsplineEncoding: x[1e6,3] -> out[1e6,195]. Per (point,dim): [x, 64 bins],
// only 4 bins nonzero; all 195M floats written => pure 780MB write stream.
//
// Round history:
//  R1 per-element: 445us (issue-bound).  R3 32pt+STG: 117.4us.
//  R4 TMA: neutral.  R5 64pt+2xTMA: 115.2us.
//  R7 persistent: 137us REGR.  R8 STG+512t: 120.9us REGR.
//  R9/R10: neutral.  R11 TMA cache_hint: no ptxas support.
//  R12 64pt + STG.cs: 108.6us <-- best (evict-first: L2 write-combining
//      retained, writeback debt between replays removed).
//  R13 STG.wt: 127us REGR (write-through kills write-combining).
//
// R14 = R12 with an 80-pt tile: fewer blocks (12500), longer uninterrupted
// .cs store bursts per block -> better sequential runs for the combiner.

static constexpr float SCALE    = 30.5f;            // (K-DEG)/(MAX-MIN) = 61/2
static constexpr float CLAMP_HI = 61.0f - 1e-6f;    // K - DEG - EPS
static constexpr int   PTS_PER_BLK = 80;            // 1e6 % 80 == 0
static constexpr int   TILE_FLOATS = PTS_PER_BLK * 195;   // 15600
static constexpr int   TILE_BYTES  = TILE_FLOATS * 4;     // 62400
static constexpr int   TILE_VEC4   = TILE_FLOATS / 4;     // 3900
static constexpr int   THREADS     = 256;
static constexpr int   NWORK       = PTS_PER_BLK * 3;     // 240 workers

__global__ __launch_bounds__(THREADS)
void bspline_enc_kernel(const float* __restrict__ xin,
                        float* __restrict__ out)
{
    extern __shared__ __align__(16) float tile[];
    const int tid = threadIdx.x;

    // Hoisted input load; latency hides under the zero phase.
    float xv = 0.0f;
    if (tid < NWORK)
        xv = __ldg(xin + (size_t)blockIdx.x * NWORK + tid);

    // Phase 1: zero the tile (float4 stores, conflict-free).
    float4 z4 = make_float4(0.f, 0.f, 0.f, 0.f);
    float4* t4 = reinterpret_cast<float4*>(tile);
#pragma unroll
    for (int i = tid; i < TILE_VEC4; i += THREADS)
        t4[i] = z4;
    __syncthreads();

    // Phase 2: 240 workers, one per (point, dim).
    if (tid < NWORK) {
        const int p = tid / 3;
        const int d = tid - p * 3;

        float xs = fminf(fmaxf((xv + 1.0f) * SCALE, 0.0f), CLAMP_HI);
        float fi = floorf(xs);
        int  idx = (int)fi;
        float u  = xs - fi;
        float u2 = u * u;
        float u3 = u2 * u;
        float om = 1.0f - u;
        float c0 = om * om * om * (1.0f / 6.0f);
        float c1 = (3.0f * u3 - 6.0f * u2 + 4.0f) * (1.0f / 6.0f);
        float c2 = (-3.0f * u3 + 3.0f * u2 + 3.0f * u + 1.0f) * (1.0f / 6.0f);
        float c3 = u3 * (1.0f / 6.0f);

        float* dst = tile + p * 195 + d * 65;
        dst[0]       = xv;
        dst[1 + idx] = c0;
        dst[2 + idx] = c1;
        dst[3 + idx] = c2;
        dst[4 + idx] = c3;
    }
    __syncthreads();

    // Phase 3: evict-first (.cs) float4 drain. Fire-and-forget.
    float4* o4 = reinterpret_cast<float4*>(out) + (size_t)blockIdx.x * TILE_VEC4;
#pragma unroll
    for (int i = tid; i < TILE_VEC4; i += THREADS)
        __stcs(o4 + i, t4[i]);
}

extern "C" void kernel_launch(void* const* d_in, const int* in_sizes, int n_in,
                              void* d_out, int out_size)
{
    const float* x = (const float*)d_in[0];
    float* out = (float*)d_out;

    static bool attr_set = false;
    if (!attr_set) {
        cudaFuncSetAttribute(bspline_enc_kernel,
                             cudaFuncAttributeMaxDynamicSharedMemorySize,
                             TILE_BYTES);
        attr_set = true;
    }

    int n_points = out_size / 195;
    int blocks   = n_points / PTS_PER_BLK;   // 12500 for N = 1e6
    bspline_enc_kernel<<<blocks, THREADS, TILE_BYTES>>>(x, out);
}

// round 16
// speedup vs baseline: 1.4324x; 1.4324x over previous
#include <cuda_runtime.h>
#include <cstdint>

// BsplineEncoding: x[1e6,3] -> out[1e6,195]. Per (point,dim): [x, 64 bins],
// only 4 bins nonzero; all 195M floats written => pure 780MB write stream.
//
// Round history:
//  R1 per-element: 445us (issue-bound).  R3 32pt+STG(default): 117.4us.
//  R4 TMA: neutral.  R5 64pt+2xTMA: 115.2us.  R7 persistent: 137us REGR.
//  R8 STG+512t: 120.9us REGR.  R9/R10: neutral.  R11: no ptxas support.
//  R12 64pt+STG.cs+256t: 108.6us <-- best (evict-first keeps L2 write-
//      combining, drops writeback debt).
//  R13 STG.wt: 127us REGR (no write-combining).
//  R14 80pt+.cs: 155.7us REGR (3 CTAs/SM starves the STG drain of warps).
//
// R15: 32pt tile + .cs — 8 CTAs/SM / 64 warps of drain fuel (STG drains are
// occupancy-fed, unlike TMA). Untested cell in the tile x policy matrix.

static constexpr float SCALE    = 30.5f;            // (K-DEG)/(MAX-MIN) = 61/2
static constexpr float CLAMP_HI = 61.0f - 1e-6f;    // K - DEG - EPS
static constexpr int   PTS_PER_BLK = 32;
static constexpr int   TILE_FLOATS = PTS_PER_BLK * 195;   // 6240
static constexpr int   TILE_VEC4   = TILE_FLOATS / 4;     // 1560
static constexpr int   THREADS     = 256;
static constexpr int   NWORK       = PTS_PER_BLK * 3;     // 96 workers

__global__ __launch_bounds__(THREADS)
void bspline_enc_kernel(const float* __restrict__ xin,
                        float* __restrict__ out)
{
    __shared__ __align__(16) float tile[TILE_FLOATS];
    const int tid = threadIdx.x;

    // Hoisted input load; latency hides under the zero phase.
    float xv = 0.0f;
    if (tid < NWORK)
        xv = __ldg(xin + (size_t)blockIdx.x * NWORK + tid);

    // Phase 1: zero the tile (float4 stores, conflict-free).
    float4 z4 = make_float4(0.f, 0.f, 0.f, 0.f);
    float4* t4 = reinterpret_cast<float4*>(tile);
#pragma unroll
    for (int i = tid; i < TILE_VEC4; i += THREADS)
        t4[i] = z4;
    __syncthreads();

    // Phase 2: 96 workers, one per (point, dim).
    if (tid < NWORK) {
        const int p = tid / 3;
        const int d = tid - p * 3;

        float xs = fminf(fmaxf((xv + 1.0f) * SCALE, 0.0f), CLAMP_HI);
        float fi = floorf(xs);
        int  idx = (int)fi;
        float u  = xs - fi;
        float u2 = u * u;
        float u3 = u2 * u;
        float om = 1.0f - u;
        float c0 = om * om * om * (1.0f / 6.0f);
        float c1 = (3.0f * u3 - 6.0f * u2 + 4.0f) * (1.0f / 6.0f);
        float c2 = (-3.0f * u3 + 3.0f * u2 + 3.0f * u + 1.0f) * (1.0f / 6.0f);
        float c3 = u3 * (1.0f / 6.0f);

        float* dst = tile + p * 195 + d * 65;
        dst[0]       = xv;
        dst[1 + idx] = c0;
        dst[2 + idx] = c1;
        dst[3 + idx] = c2;
        dst[4 + idx] = c3;
    }
    __syncthreads();

    // Phase 3: evict-first (.cs) float4 drain. Fire-and-forget — block
    // retires at store issue; 8 CTAs/SM keep the store pipe fed.
    float4* o4 = reinterpret_cast<float4*>(out) + (size_t)blockIdx.x * TILE_VEC4;
#pragma unroll
    for (int i = tid; i < TILE_VEC4; i += THREADS)
        __stcs(o4 + i, t4[i]);
}

extern "C" void kernel_launch(void* const* d_in, const int* in_sizes, int n_in,
                              void* d_out, int out_size)
{
    const float* x = (const float*)d_in[0];
    float* out = (float*)d_out;

    int n_points = out_size / 195;
    int blocks   = n_points / PTS_PER_BLK;   // 31250 for N = 1e6
    bspline_enc_kernel<<<blocks, THREADS>>>(x, out);
}

// round 17
// speedup vs baseline: 1.4350x; 1.0018x over previous
#include <cuda_runtime.h>
#include <cstdint>

// BsplineEncoding: x[1e6,3] -> out[1e6,195]. Per (point,dim): [x, 64 bins],
// only 4 bins nonzero; all 195M floats written => pure 780MB write stream.
// Wall-clock BW at best config: 7.2 TB/s = ~90% of 8TB/s spec (roofline).
//
// Round history:
//  R1 per-element: 445us.  R3 32pt+STG: 117.4us.  R4 TMA: neutral.
//  R5 64pt+2xTMA: 115.2us.  R7 persistent: 137 REGR.  R8 512t: 121 REGR.
//  R9/R10 neutral.  R11 no ptxas support.  R12 64pt+STG.cs: 108.6 <-- best.
//  R13 .wt: 127 REGR (no write-combining).  R14 80pt+.cs: 156 REGR
//  (3 CTAs/SM starves STG drain).  R15 32pt+.cs: 108.7 (tie).
//
// R16 = R15 + register-batched drain: load all 6 float4s from smem first,
// then issue 6 .cs stores back-to-back — overlaps LDS latencies and gives
// the L2 write-combiner a dense 6-line sequential burst per thread.

static constexpr float SCALE    = 30.5f;            // (K-DEG)/(MAX-MIN) = 61/2
static constexpr float CLAMP_HI = 61.0f - 1e-6f;    // K - DEG - EPS
static constexpr int   PTS_PER_BLK = 32;
static constexpr int   TILE_FLOATS = PTS_PER_BLK * 195;   // 6240
static constexpr int   TILE_VEC4   = TILE_FLOATS / 4;     // 1560
static constexpr int   THREADS     = 256;
static constexpr int   NWORK       = PTS_PER_BLK * 3;     // 96 workers
static constexpr int   FULL_ITERS  = TILE_VEC4 / THREADS; // 6 (1536)
static constexpr int   TAIL        = TILE_VEC4 - FULL_ITERS * THREADS; // 24

__global__ __launch_bounds__(THREADS)
void bspline_enc_kernel(const float* __restrict__ xin,
                        float* __restrict__ out)
{
    __shared__ __align__(16) float tile[TILE_FLOATS];
    const int tid = threadIdx.x;

    // Hoisted input load; latency hides under the zero phase.
    float xv = 0.0f;
    if (tid < NWORK)
        xv = __ldg(xin + (size_t)blockIdx.x * NWORK + tid);

    // Phase 1: zero the tile (float4 stores, conflict-free).
    float4 z4 = make_float4(0.f, 0.f, 0.f, 0.f);
    float4* t4 = reinterpret_cast<float4*>(tile);
#pragma unroll
    for (int i = tid; i < TILE_VEC4; i += THREADS)
        t4[i] = z4;
    __syncthreads();

    // Phase 2: 96 workers, one per (point, dim).
    if (tid < NWORK) {
        const int p = tid / 3;
        const int d = tid - p * 3;

        float xs = fminf(fmaxf((xv + 1.0f) * SCALE, 0.0f), CLAMP_HI);
        float fi = floorf(xs);
        int  idx = (int)fi;
        float u  = xs - fi;
        float u2 = u * u;
        float u3 = u2 * u;
        float om = 1.0f - u;
        float c0 = om * om * om * (1.0f / 6.0f);
        float c1 = (3.0f * u3 - 6.0f * u2 + 4.0f) * (1.0f / 6.0f);
        float c2 = (-3.0f * u3 + 3.0f * u2 + 3.0f * u + 1.0f) * (1.0f / 6.0f);
        float c3 = u3 * (1.0f / 6.0f);

        float* dst = tile + p * 195 + d * 65;
        dst[0]       = xv;
        dst[1 + idx] = c0;
        dst[2 + idx] = c1;
        dst[3 + idx] = c2;
        dst[4 + idx] = c3;
    }
    __syncthreads();

    // Phase 3: register-batched evict-first drain. All LDS first (latencies
    // overlap), then 6 back-to-back .cs stores (dense sequential burst).
    float4* o4 = reinterpret_cast<float4*>(out) + (size_t)blockIdx.x * TILE_VEC4;

    float4 v[FULL_ITERS];
#pragma unroll
    for (int k = 0; k < FULL_ITERS; ++k)
        v[k] = t4[tid + k * THREADS];
#pragma unroll
    for (int k = 0; k < FULL_ITERS; ++k)
        __stcs(o4 + tid + k * THREADS, v[k]);

    // Tail: last 24 vec4s.
    if (tid < TAIL)
        __stcs(o4 + FULL_ITERS * THREADS + tid, t4[FULL_ITERS * THREADS + tid]);
}

extern "C" void kernel_launch(void* const* d_in, const int* in_sizes, int n_in,
                              void* d_out, int out_size)
{
    const float* x = (const float*)d_in[0];
    float* out = (float*)d_out;

    int n_points = out_size / 195;
    int blocks   = n_points / PTS_PER_BLK;   // 31250 for N = 1e6
    bspline_enc_kernel<<<blocks, THREADS>>>(x, out);
}